// round 6
// baseline (speedup 1.0000x reference)
#include <cuda_runtime.h>
#include <math.h>
#include <stdint.h>

#define B_  16
#define LC  2048
#define LQ  1024
#define D_  512
#define BK  32

// ---------------- scratch (device globals; cudaMalloc forbidden) ----------
__device__ float g_S  [(size_t)B_ * LC * LQ];  // 128 MiB: S[b,i,j]
__device__ float g_A  [(size_t)B_ * LC * LQ];  // 128 MiB: A[b,i,j] (tf32-rounded)
__device__ float g_c32[(size_t)B_ * LC * D_];  // 64 MiB : rna(ctx)
__device__ float g_qm [(size_t)LQ * D_];       // 2 MiB  : rna(q * wm) [j,k]
__device__ float g_cb [B_ * LC];               // context @ wc
__device__ float g_m  [B_ * LQ];               // softmax max over i per (b,j)
__device__ float g_w2 [B_ * LQ];               // qmask[j] / Z[b,j]
__device__ float g_qmask[LQ];
__device__ float g_mp [4][B_ * LQ];            // strip partial max
__device__ float g_zp [4][B_ * LQ];            // strip partial Z

// ---------------- helpers ---------------------------------------------------
__device__ __forceinline__ uint32_t smem_u32(const void* p) {
    uint32_t a;
    asm("{ .reg .u64 t; cvta.to.shared.u64 t, %1; cvt.u32.u64 %0, t; }" : "=r"(a) : "l"(p));
    return a;
}
__device__ __forceinline__ float rna_tf32(float x) {
    float y; asm("cvt.rna.tf32.f32 %0, %1;" : "=f"(y) : "f"(x)); return y;
}
#define CP16(sm, gp) \
    asm volatile("cp.async.cg.shared.global [%0], [%1], 16;" :: "r"(sm), "l"(gp))
#define CP_COMMIT() asm volatile("cp.async.commit_group;" ::: "memory")

#define MMA(c, a, b) \
    asm volatile("mma.sync.aligned.m16n8k8.row.col.f32.tf32.tf32.f32 " \
        "{%0,%1,%2,%3},{%4,%5,%6,%7},{%8,%9},{%0,%1,%2,%3};" \
        : "+f"((c)[0]), "+f"((c)[1]), "+f"((c)[2]), "+f"((c)[3]) \
        : "r"((a)[0]), "r"((a)[1]), "r"((a)[2]), "r"((a)[3]), \
          "r"((b)[0]), "r"((b)[1]))

// ---------------- kernel: cb = C@wc per row, qmask per query row ----------
__global__ void k_bias(const float* __restrict__ ctx,
                       const float* __restrict__ q,
                       const float* __restrict__ w) {
    int gwarp = (blockIdx.x * blockDim.x + threadIdx.x) >> 5;
    int lane  = threadIdx.x & 31;
    const int nrows = B_ * LC + LQ;
    if (gwarp >= nrows) return;
    if (gwarp < B_ * LC) {
        const float4* row = (const float4*)(ctx + (size_t)gwarp * D_);
        const float4* wc4 = (const float4*)w;
        float s = 0.f;
        #pragma unroll 4
        for (int k = lane; k < D_ / 4; k += 32) {
            float4 a = row[k], b = wc4[k];
            s += a.x * b.x + a.y * b.y + a.z * b.z + a.w * b.w;
        }
        #pragma unroll
        for (int o = 16; o; o >>= 1) s += __shfl_xor_sync(~0u, s, o);
        if (!lane) g_cb[gwarp] = s;
    } else {
        int j = gwarp - B_ * LC;
        const float4* row = (const float4*)(q + (size_t)j * D_);
        float s = 0.f;
        #pragma unroll 4
        for (int k = lane; k < D_ / 4; k += 32) {
            float4 a = row[k];
            s += a.x + a.y + a.z + a.w;
        }
        #pragma unroll
        for (int o = 16; o; o >>= 1) s += __shfl_xor_sync(~0u, s, o);
        if (!lane) g_qmask[j] = (s != 0.0f) ? 1.0f : 0.0f;
    }
}

// ---------------- kernel: pre-round ctx to tf32 ----------------------------
__global__ void k_round(const float* __restrict__ ctx) {
    size_t idx = (size_t)blockIdx.x * blockDim.x + threadIdx.x;
    float4 v = ((const float4*)ctx)[idx];
    float4 o = { rna_tf32(v.x), rna_tf32(v.y), rna_tf32(v.z), rna_tf32(v.w) };
    ((float4*)g_c32)[idx] = o;
}

// ---------------- kernel: qm[j,k] = rna(q[j,k] * wm[k]) --------------------
__global__ void k_qm(const float* __restrict__ q, const float* __restrict__ w) {
    int j = blockIdx.x, t = threadIdx.x;   // 128 threads * float4 = 512
    const float4* q4 = (const float4*)(q + (size_t)j * D_);
    const float4* w4 = (const float4*)(w + 2 * D_);
    float4 a = q4[t], b = w4[t];
    float4 o = { rna_tf32(a.x * b.x), rna_tf32(a.y * b.y),
                 rna_tf32(a.z * b.z), rna_tf32(a.w * b.w) };
    ((float4*)(g_qm + (size_t)j * D_))[t] = o;
}

// ---------------- tf32 mma.sync GEMM, 128x128 block, 8 warps (64x32 each) --
// All operands pre-rounded to tf32: fragments load raw bits, no cvt in loop.
// MODE 0: S[b,i,j] = c32[b,i,:]·qm[j,:] + cb[b,i]        (K = 512)
//         A smem [m=128][k], stride 36   B smem [n=128][k], stride 36
// MODE 1: H[b,j,d] = A[b,:,j]·c32[b,:,d]                 (K = 2048, k = i)
//         A smem [k=32][m=128], stride 132  B smem [k=32][n=128], stride 132
template<int MODE>
__global__ __launch_bounds__(256, 2) void k_mma(float* __restrict__ gOut) {
    constexpr int KTOT  = MODE ? LC : D_;
    constexpr int NKC   = KTOT / BK;
    constexpr int STAGE = MODE ? (BK * 132) : (128 * 36);  // floats per operand

    extern __shared__ float sh[];
    float* sAb = sh;               // [2][STAGE]
    float* sBb = sh + 2 * STAGE;   // [2][STAGE]

    const int tid = threadIdx.x;
    const int b   = blockIdx.z;
    const int x0  = blockIdx.x * 128;   // MODE0: j0 ; MODE1: d0
    const int y0  = blockIdx.y * 128;   // MODE0: i0 ; MODE1: j0

    const float* Abase;
    const float* Bbase;
    if (MODE == 0) {
        Abase = g_c32 + ((size_t)b * LC + y0) * D_;          // ctx rows i
        Bbase = g_qm + (size_t)x0 * D_;                      // qm rows j
    } else {
        Abase = g_A + (size_t)b * LC * LQ + y0;              // A[b, k, j0+..]
        Bbase = g_c32 + (size_t)b * LC * D_ + x0;            // ctx[b, k, d0+..]
    }

    auto load = [&](int c, int stage) {
        float* dA = sAb + stage * STAGE;
        float* dB = sBb + stage * STAGE;
        const int k0 = c * BK;
        if (MODE == 0) {
            #pragma unroll
            for (int p = 0; p < 4; p++) {
                int idx = tid + p * 256;          // 1024 cp16 per operand
                int row = idx >> 3, seg = idx & 7;
                CP16(smem_u32(dA + row * 36 + seg * 4),
                     Abase + (size_t)row * D_ + k0 + seg * 4);
                CP16(smem_u32(dB + row * 36 + seg * 4),
                     Bbase + (size_t)row * D_ + k0 + seg * 4);
            }
        } else {
            #pragma unroll
            for (int p = 0; p < 4; p++) {
                int idx = tid + p * 256;          // 32 rows x 32 cp16
                int row = idx >> 5, seg = idx & 31;
                CP16(smem_u32(dA + row * 132 + seg * 4),
                     Abase + (size_t)(k0 + row) * LQ + seg * 4);
                CP16(smem_u32(dB + row * 132 + seg * 4),
                     Bbase + (size_t)(k0 + row) * D_ + seg * 4);
            }
        }
    };

    const int lane  = tid & 31, wrp = tid >> 5;
    const int mbase = (wrp & 1) * 64, nbase = (wrp >> 1) * 32;
    const int lr    = lane >> 2, lk = lane & 3;

    float acc[4][4][4];
    #pragma unroll
    for (int mt = 0; mt < 4; mt++)
        #pragma unroll
        for (int nt = 0; nt < 4; nt++)
            #pragma unroll
            for (int e = 0; e < 4; e++) acc[mt][nt][e] = 0.f;

    auto compute = [&](int stage) {
        const uint32_t* A  = (const uint32_t*)(sAb + stage * STAGE);
        const uint32_t* Bp = (const uint32_t*)(sBb + stage * STAGE);
        #pragma unroll
        for (int kk = 0; kk < BK; kk += 8) {
            uint32_t af[4][4], bf[4][2];
            #pragma unroll
            for (int mt = 0; mt < 4; mt++) {
                int r = mbase + mt * 16 + lr;
                if (MODE == 0) {
                    af[mt][0] = A[r * 36 + kk + lk];
                    af[mt][1] = A[(r + 8) * 36 + kk + lk];
                    af[mt][2] = A[r * 36 + kk + lk + 4];
                    af[mt][3] = A[(r + 8) * 36 + kk + lk + 4];
                } else {
                    af[mt][0] = A[(kk + lk) * 132 + r];
                    af[mt][1] = A[(kk + lk) * 132 + r + 8];
                    af[mt][2] = A[(kk + lk + 4) * 132 + r];
                    af[mt][3] = A[(kk + lk + 4) * 132 + r + 8];
                }
            }
            #pragma unroll
            for (int nt = 0; nt < 4; nt++) {
                int cix = nbase + nt * 8 + lr;
                if (MODE == 0) {
                    bf[nt][0] = Bp[cix * 36 + kk + lk];
                    bf[nt][1] = Bp[cix * 36 + kk + lk + 4];
                } else {
                    bf[nt][0] = Bp[(kk + lk) * 132 + cix];
                    bf[nt][1] = Bp[(kk + lk + 4) * 132 + cix];
                }
            }
            #pragma unroll
            for (int mt = 0; mt < 4; mt++)
                #pragma unroll
                for (int nt = 0; nt < 4; nt++)
                    MMA(acc[mt][nt], af[mt], bf[nt]);
        }
    };

    load(0, 0); CP_COMMIT();
    load(1, 1); CP_COMMIT();
    for (int c = 0; c < NKC; c++) {
        asm volatile("cp.async.wait_group 1;" ::: "memory");
        __syncthreads();
        compute(c & 1);
        __syncthreads();
        if (c + 2 < NKC) load(c + 2, c & 1);
        CP_COMMIT();
    }

    if (MODE == 0) {
        #pragma unroll
        for (int mt = 0; mt < 4; mt++) {
            int i = y0 + mbase + mt * 16 + lr;
            float c0 = g_cb[b * LC + i];
            float c8 = g_cb[b * LC + i + 8];
            #pragma unroll
            for (int nt = 0; nt < 4; nt++) {
                int j = x0 + nbase + nt * 8 + 2 * lk;
                float2 v0 = make_float2(acc[mt][nt][0] + c0, acc[mt][nt][1] + c0);
                float2 v1 = make_float2(acc[mt][nt][2] + c8, acc[mt][nt][3] + c8);
                *(float2*)(g_S + ((size_t)(b * LC + i)) * LQ + j)     = v0;
                *(float2*)(g_S + ((size_t)(b * LC + i + 8)) * LQ + j) = v1;
            }
        }
    } else {
        #pragma unroll
        for (int mt = 0; mt < 4; mt++) {
            int j = y0 + mbase + mt * 16 + lr;
            #pragma unroll
            for (int nt = 0; nt < 4; nt++) {
                int d = x0 + nbase + nt * 8 + 2 * lk;
                float2 v0 = make_float2(acc[mt][nt][0], acc[mt][nt][1]);
                float2 v1 = make_float2(acc[mt][nt][2], acc[mt][nt][3]);
                *(float2*)(gOut + ((size_t)(b * LQ + j)) * D_ + d)     = v0;
                *(float2*)(gOut + ((size_t)(b * LQ + j + 8)) * D_ + d) = v1;
            }
        }
    }
}

// ---------------- kernel: strip-partial max + Z over i (phase 1) -----------
__global__ void k_stats1() {
    const int b  = blockIdx.y;
    const int j  = blockIdx.x * 128 + threadIdx.x;
    const int st = blockIdx.z;                  // 0..3 strip
    const int ty = threadIdx.y;                 // 0..3 within strip
    const int ibeg = st * (LC / 4);
    const float* Sp = g_S + (size_t)b * LC * LQ + j;
    float m = -1e30f, Z = 0.f;
    for (int i = ibeg + ty; i < ibeg + LC / 4; i += 4) {
        float s = Sp[(size_t)i * LQ];
        if (s > m) { Z *= __expf(m - s); m = s; }
        Z += __expf(s - m);
    }
    __shared__ float smm[4][128], smz[4][128];
    smm[ty][threadIdx.x] = m;
    smz[ty][threadIdx.x] = Z;
    __syncthreads();
    if (ty == 0) {
        float mm = m;
        #pragma unroll
        for (int t = 1; t < 4; t++) mm = fmaxf(mm, smm[t][threadIdx.x]);
        float ZZ = 0.f;
        #pragma unroll
        for (int t = 0; t < 4; t++) ZZ += smz[t][threadIdx.x] * __expf(smm[t][threadIdx.x] - mm);
        g_mp[st][b * LQ + j] = mm;
        g_zp[st][b * LQ + j] = ZZ;
    }
}

// ---------------- kernel: combine strips (phase 2) --------------------------
__global__ void k_stats2() {
    int idx = blockIdx.x * blockDim.x + threadIdx.x;   // b*LQ + j
    float m0 = g_mp[0][idx], m1 = g_mp[1][idx];
    float m2 = g_mp[2][idx], m3 = g_mp[3][idx];
    float M = fmaxf(fmaxf(m0, m1), fmaxf(m2, m3));
    float Z = g_zp[0][idx] * __expf(m0 - M) + g_zp[1][idx] * __expf(m1 - M)
            + g_zp[2][idx] * __expf(m2 - M) + g_zp[3][idx] * __expf(m3 - M);
    g_m [idx] = M;
    g_w2[idx] = g_qmask[idx & (LQ - 1)] / Z;
}

// ---------------- kernel: A[b,i,j] (tf32) + colsum + G (fused) --------------
__global__ __launch_bounds__(256) void k_colsum_AG(const float* __restrict__ ctx,
                                                   float* __restrict__ G) {
    const int b = blockIdx.y;
    __shared__ float sm[LQ], sw[LQ];
    for (int t = threadIdx.x; t < LQ; t += 256) {
        sm[t] = g_m [b * LQ + t];
        sw[t] = g_w2[b * LQ + t];
    }
    __syncthreads();
    const int wrp = threadIdx.x >> 5, lane = threadIdx.x & 31;
    const size_t row = (size_t)b * LC + blockIdx.x * 8 + wrp;
    const float4* S4 = (const float4*)(g_S + row * LQ);
    float4* A4 = (float4*)(g_A + row * LQ);
    float cs = 0.f;
    #pragma unroll 2
    for (int t = lane; t < LQ / 4; t += 32) {
        float4 s = S4[t];
        int j = t * 4;
        float a0 = __expf(s.x - sm[j + 0]) * sw[j + 0];
        float a1 = __expf(s.y - sm[j + 1]) * sw[j + 1];
        float a2 = __expf(s.z - sm[j + 2]) * sw[j + 2];
        float a3 = __expf(s.w - sm[j + 3]) * sw[j + 3];
        cs += (a0 + a1) + (a2 + a3);
        A4[t] = make_float4(rna_tf32(a0), rna_tf32(a1), rna_tf32(a2), rna_tf32(a3));
    }
    #pragma unroll
    for (int o = 16; o; o >>= 1) cs += __shfl_xor_sync(~0u, cs, o);
    const float4* c4 = (const float4*)(ctx + row * D_);
    float4* g4 = (float4*)(G + row * 2 * D_);
    #pragma unroll
    for (int t = lane; t < D_ / 4; t += 32) {
        float4 v = c4[t];
        g4[t] = v;
        g4[128 + t] = make_float4(v.x * cs, v.y * cs, v.z * cs, v.w * cs);
    }
}

// ---------------- launch -----------------------------------------------------
extern "C" void kernel_launch(void* const* d_in, const int* in_sizes, int n_in,
                              void* d_out, int out_size) {
    const float *ctx = nullptr, *q = nullptr, *w = nullptr;
    for (int i = 0; i < n_in; i++) {
        if      (in_sizes[i] == B_ * LC * D_) ctx = (const float*)d_in[i];
        else if (in_sizes[i] == LQ * D_)      q   = (const float*)d_in[i];
        else if (in_sizes[i] == 3 * D_)       w   = (const float*)d_in[i];
    }
    float* G = (float*)d_out;                              // (B, LC, 2D)
    float* H = (float*)d_out + (size_t)B_ * LC * 2 * D_;   // (B, LQ, D)

    const int smem0 = 2 * 2 * 128 * 36 * 4;   // 73728
    const int smem1 = 2 * 2 * BK * 132 * 4;   // 67584
    cudaFuncSetAttribute(k_mma<0>, cudaFuncAttributeMaxDynamicSharedMemorySize, smem0);
    cudaFuncSetAttribute(k_mma<1>, cudaFuncAttributeMaxDynamicSharedMemorySize, smem1);

    k_bias     <<<(B_ * LC + LQ + 7) / 8, 256>>>(ctx, q, w);
    k_round    <<<(B_ * LC * D_ / 4) / 256, 256>>>(ctx);
    k_qm       <<<LQ, 128>>>(q, w);
    k_mma<0>   <<<dim3(LQ / 128, LC / 128, B_), 256, smem0>>>(nullptr);
    k_stats1   <<<dim3(LQ / 128, B_, 4), dim3(128, 4)>>>();
    k_stats2   <<<B_ * LQ / 256, 256>>>();
    k_colsum_AG<<<dim3(LC / 8, B_), 256>>>(ctx, G);
    k_mma<1>   <<<dim3(D_ / 128, LQ / 128, B_), 256, smem1>>>(H);
}

// round 7
// speedup vs baseline: 1.0826x; 1.0826x over previous
#include <cuda_runtime.h>
#include <math.h>
#include <stdint.h>

#define B_  16
#define LC  2048
#define LQ  1024
#define D_  512

// ---------------- scratch (device globals; cudaMalloc forbidden) ----------
__device__ float g_S  [(size_t)B_ * LC * LQ];  // 128 MiB: S[b,i,j]
__device__ float g_At [(size_t)B_ * LQ * LC];  // 128 MiB: A^T[b,j,i] (tf32-rounded)
__device__ float g_c32[(size_t)B_ * LC * D_];  // 64 MiB : rna(ctx) [b,i,d]
__device__ float g_cT [(size_t)B_ * D_ * LC];  // 64 MiB : rna(ctx)^T [b,d,i]
__device__ float g_qm [(size_t)LQ * D_];       // 2 MiB  : rna(q * wm) [j,k]
__device__ float g_cb [B_ * LC];               // context @ wc
__device__ float g_m  [B_ * LQ];               // softmax max over i per (b,j)
__device__ float g_w2 [B_ * LQ];               // qmask[j] / Z[b,j]
__device__ float g_qmask[LQ];
__device__ float g_mp [4][B_ * LQ];            // strip partial max
__device__ float g_zp [4][B_ * LQ];            // strip partial Z

// ---------------- helpers ---------------------------------------------------
__device__ __forceinline__ uint32_t smem_u32(const void* p) {
    uint32_t a;
    asm("{ .reg .u64 t; cvta.to.shared.u64 t, %1; cvt.u32.u64 %0, t; }" : "=r"(a) : "l"(p));
    return a;
}
__device__ __forceinline__ float rna_tf32(float x) {
    float y; asm("cvt.rna.tf32.f32 %0, %1;" : "=f"(y) : "f"(x)); return y;
}
#define CP16(sm, gp) \
    asm volatile("cp.async.cg.shared.global [%0], [%1], 16;" :: "r"(sm), "l"(gp))
#define CP_COMMIT() asm volatile("cp.async.commit_group;" ::: "memory")

#define LDSM4(r0, r1, r2, r3, addr) \
    asm volatile("ldmatrix.sync.aligned.m8n8.x4.shared.b16 {%0,%1,%2,%3}, [%4];" \
        : "=r"(r0), "=r"(r1), "=r"(r2), "=r"(r3) : "r"(addr))

#define MMA(c, a, b) \
    asm volatile("mma.sync.aligned.m16n8k8.row.col.f32.tf32.tf32.f32 " \
        "{%0,%1,%2,%3},{%4,%5,%6,%7},{%8,%9},{%0,%1,%2,%3};" \
        : "+f"((c)[0]), "+f"((c)[1]), "+f"((c)[2]), "+f"((c)[3]) \
        : "r"((a)[0]), "r"((a)[1]), "r"((a)[2]), "r"((a)[3]), \
          "r"((b)[0]), "r"((b)[1]))

// ---------------- kernel: cb = C@wc per row, qmask per query row ----------
__global__ void k_bias(const float* __restrict__ ctx,
                       const float* __restrict__ q,
                       const float* __restrict__ w) {
    int gwarp = (blockIdx.x * blockDim.x + threadIdx.x) >> 5;
    int lane  = threadIdx.x & 31;
    const int nrows = B_ * LC + LQ;
    if (gwarp >= nrows) return;
    if (gwarp < B_ * LC) {
        const float4* row = (const float4*)(ctx + (size_t)gwarp * D_);
        const float4* wc4 = (const float4*)w;
        float s = 0.f;
        #pragma unroll 4
        for (int k = lane; k < D_ / 4; k += 32) {
            float4 a = row[k], b = wc4[k];
            s += a.x * b.x + a.y * b.y + a.z * b.z + a.w * b.w;
        }
        #pragma unroll
        for (int o = 16; o; o >>= 1) s += __shfl_xor_sync(~0u, s, o);
        if (!lane) g_cb[gwarp] = s;
    } else {
        int j = gwarp - B_ * LC;
        const float4* row = (const float4*)(q + (size_t)j * D_);
        float s = 0.f;
        #pragma unroll 4
        for (int k = lane; k < D_ / 4; k += 32) {
            float4 a = row[k];
            s += a.x + a.y + a.z + a.w;
        }
        #pragma unroll
        for (int o = 16; o; o >>= 1) s += __shfl_xor_sync(~0u, s, o);
        if (!lane) g_qmask[j] = (s != 0.0f) ? 1.0f : 0.0f;
    }
}

// ---------------- kernel: round ctx -> c32 [i][d], transpose -> cT [d][i] ---
__global__ void k_prep(const float* __restrict__ ctx) {
    __shared__ float t[32][33];
    int b = blockIdx.z, i0 = blockIdx.y << 5, d0 = blockIdx.x << 5;
    int tx = threadIdx.x, ty = threadIdx.y;
    #pragma unroll
    for (int q = 0; q < 4; q++) {
        int r = ty + q * 8;
        float v = rna_tf32(ctx[((size_t)b * LC + i0 + r) * D_ + d0 + tx]);
        g_c32[((size_t)b * LC + i0 + r) * D_ + d0 + tx] = v;
        t[r][tx] = v;
    }
    __syncthreads();
    #pragma unroll
    for (int q = 0; q < 4; q++) {
        int r = ty + q * 8;
        g_cT[((size_t)b * D_ + d0 + r) * LC + i0 + tx] = t[tx][r];
    }
}

// ---------------- kernel: qm[j,k] = rna(q[j,k] * wm[k]) --------------------
__global__ void k_qm(const float* __restrict__ q, const float* __restrict__ w) {
    int j = blockIdx.x, t = threadIdx.x;
    const float4* q4 = (const float4*)(q + (size_t)j * D_);
    const float4* w4 = (const float4*)(w + 2 * D_);
    float4 a = q4[t], b = w4[t];
    float4 o = { rna_tf32(a.x * b.x), rna_tf32(a.y * b.y),
                 rna_tf32(a.z * b.z), rna_tf32(a.w * b.w) };
    ((float4*)(g_qm + (size_t)j * D_))[t] = o;
}

// ---------------- unified K-major tf32 GEMM --------------------------------
// Block 256(m) x 128(n), BK=32, 8 warps of 64x64, 4-stage cp.async,
// single __syncthreads per chunk, ldmatrix fragment loads.
// MODE 0: m=i (256 of LC), n=j, K=D_  : S = c32 · qm^T + cb
// MODE 1: m=j (256 of LQ), n=d, K=LC : H = At · cT^T
#define ASZ (256 * 36)            // A floats per stage
#define BSZ (128 * 36)            // B floats per stage
#define STG (ASZ + BSZ)           // 13824 floats = 55296 B
#define GEMM_SMEM (4 * STG * 4)   // 221184 B

template<int MODE>
__global__ __launch_bounds__(256, 1) void k_mma(float* __restrict__ gOut) {
    constexpr int KTOT = MODE ? LC : D_;
    constexpr int NKC  = KTOT / 32;

    extern __shared__ float sh[];
    const int tid  = threadIdx.x;
    const int b    = blockIdx.z;
    const int x0   = blockIdx.x * 128;   // n origin
    const int y0   = blockIdx.y * 256;   // m origin

    const float* Abase = MODE ? g_At + ((size_t)b * LQ + y0) * LC
                              : g_c32 + ((size_t)b * LC + y0) * D_;
    const float* Bbase = MODE ? g_cT + ((size_t)b * D_ + x0) * LC
                              : g_qm + (size_t)x0 * D_;

    auto load = [&](int c, int st) {
        float* dA = sh + st * STG;
        float* dB = dA + ASZ;
        const int k0 = c * 32;
        #pragma unroll
        for (int p = 0; p < 8; p++) {               // A: 256 rows x 8 segs
            int idx = tid + p * 256;
            int row = idx >> 3, seg = idx & 7;
            CP16(smem_u32(dA + row * 36 + seg * 4),
                 Abase + (size_t)row * KTOT + k0 + seg * 4);
        }
        #pragma unroll
        for (int p = 0; p < 4; p++) {               // B: 128 rows x 8 segs
            int idx = tid + p * 256;
            int row = idx >> 3, seg = idx & 7;
            CP16(smem_u32(dB + row * 36 + seg * 4),
                 Bbase + (size_t)row * KTOT + k0 + seg * 4);
        }
    };

    const int lane  = tid & 31, wrp = tid >> 5;
    const int mbase = (wrp & 3) * 64;               // 4 warps along m
    const int nbase = (wrp >> 2) * 64;              // 2 warps along n
    const int lr    = lane >> 2, lk = lane & 3;

    // ldmatrix per-thread byte offsets (within a stage)
    // A matrices order: (r+0,kk),(r+8,kk),(r+0,kk+4),(r+8,kk+4)
    const uint32_t aoff = ((mbase + ((lane >> 3) & 1) * 8 + (lane & 7)) * 36
                           + ((lane >> 4) & 1) * 4) * 4;
    // B matrices order: (n+0,kk),(n+0,kk+4),(n+8,kk),(n+8,kk+4)
    const uint32_t boff = ((nbase + ((lane >> 4) & 1) * 8 + (lane & 7)) * 36
                           + ((lane >> 3) & 1) * 4) * 4;

    float acc[4][8][4];
    #pragma unroll
    for (int mt = 0; mt < 4; mt++)
        #pragma unroll
        for (int nt = 0; nt < 8; nt++)
            #pragma unroll
            for (int e = 0; e < 4; e++) acc[mt][nt][e] = 0.f;

    auto compute = [&](int st) {
        const uint32_t aB = smem_u32(sh + st * STG) + aoff;
        const uint32_t bB = smem_u32(sh + st * STG + ASZ) + boff;
        #pragma unroll
        for (int kk = 0; kk < 32; kk += 8) {
            uint32_t af[4][4], bf[8][2];
            #pragma unroll
            for (int mt = 0; mt < 4; mt++)
                LDSM4(af[mt][0], af[mt][1], af[mt][2], af[mt][3],
                      aB + (mt * 16 * 36 + kk) * 4);
            #pragma unroll
            for (int p = 0; p < 4; p++)
                LDSM4(bf[2 * p][0], bf[2 * p][1], bf[2 * p + 1][0], bf[2 * p + 1][1],
                      bB + (p * 16 * 36 + kk) * 4);
            #pragma unroll
            for (int mt = 0; mt < 4; mt++)
                #pragma unroll
                for (int nt = 0; nt < 8; nt++)
                    MMA(acc[mt][nt], af[mt], bf[nt]);
        }
    };

    load(0, 0); CP_COMMIT();
    load(1, 1); CP_COMMIT();
    load(2, 2); CP_COMMIT();
    for (int c = 0; c < NKC; c++) {
        asm volatile("cp.async.wait_group 2;" ::: "memory");
        __syncthreads();                 // all warps done with stage (c-1)&3
        if (c + 3 < NKC) load(c + 3, (c + 3) & 3);
        CP_COMMIT();
        compute(c & 3);
    }

    // ---- epilogue
    if (MODE == 0) {
        #pragma unroll
        for (int mt = 0; mt < 4; mt++) {
            int i = y0 + mbase + mt * 16 + lr;
            float c0 = g_cb[b * LC + i];
            float c8 = g_cb[b * LC + i + 8];
            #pragma unroll
            for (int nt = 0; nt < 8; nt++) {
                int j = x0 + nbase + nt * 8 + 2 * lk;
                float2 v0 = make_float2(acc[mt][nt][0] + c0, acc[mt][nt][1] + c0);
                float2 v1 = make_float2(acc[mt][nt][2] + c8, acc[mt][nt][3] + c8);
                *(float2*)(g_S + ((size_t)(b * LC + i)) * LQ + j)     = v0;
                *(float2*)(g_S + ((size_t)(b * LC + i + 8)) * LQ + j) = v1;
            }
        }
    } else {
        #pragma unroll
        for (int mt = 0; mt < 4; mt++) {
            int j = y0 + mbase + mt * 16 + lr;
            #pragma unroll
            for (int nt = 0; nt < 8; nt++) {
                int d = x0 + nbase + nt * 8 + 2 * lk;
                float2 v0 = make_float2(acc[mt][nt][0], acc[mt][nt][1]);
                float2 v1 = make_float2(acc[mt][nt][2], acc[mt][nt][3]);
                *(float2*)(gOut + ((size_t)(b * LQ + j)) * D_ + d)     = v0;
                *(float2*)(gOut + ((size_t)(b * LQ + j + 8)) * D_ + d) = v1;
            }
        }
    }
}

// ---------------- kernel: strip-partial max + Z over i (phase 1) -----------
__global__ void k_stats1() {
    const int b  = blockIdx.y;
    const int j  = blockIdx.x * 128 + threadIdx.x;
    const int st = blockIdx.z;
    const int ty = threadIdx.y;
    const int ibeg = st * (LC / 4);
    const float* Sp = g_S + (size_t)b * LC * LQ + j;
    float m = -1e30f, Z = 0.f;
    for (int i = ibeg + ty; i < ibeg + LC / 4; i += 4) {
        float s = Sp[(size_t)i * LQ];
        if (s > m) { Z *= __expf(m - s); m = s; }
        Z += __expf(s - m);
    }
    __shared__ float smm[4][128], smz[4][128];
    smm[ty][threadIdx.x] = m;
    smz[ty][threadIdx.x] = Z;
    __syncthreads();
    if (ty == 0) {
        float mm = m;
        #pragma unroll
        for (int t = 1; t < 4; t++) mm = fmaxf(mm, smm[t][threadIdx.x]);
        float ZZ = 0.f;
        #pragma unroll
        for (int t = 0; t < 4; t++) ZZ += smz[t][threadIdx.x] * __expf(smm[t][threadIdx.x] - mm);
        g_mp[st][b * LQ + j] = mm;
        g_zp[st][b * LQ + j] = ZZ;
    }
}

// ---------------- kernel: combine strips (phase 2) --------------------------
__global__ void k_stats2() {
    int idx = blockIdx.x * blockDim.x + threadIdx.x;
    float m0 = g_mp[0][idx], m1 = g_mp[1][idx];
    float m2 = g_mp[2][idx], m3 = g_mp[3][idx];
    float M = fmaxf(fmaxf(m0, m1), fmaxf(m2, m3));
    float Z = g_zp[0][idx] * __expf(m0 - M) + g_zp[1][idx] * __expf(m1 - M)
            + g_zp[2][idx] * __expf(m2 - M) + g_zp[3][idx] * __expf(m3 - M);
    g_m [idx] = M;
    g_w2[idx] = g_qmask[idx & (LQ - 1)] / Z;
}

// ---------------- kernel: A^T tiles + colsum + G (fused) --------------------
// block: 32 i-rows x all j; writes At[b,j,i] transposed, colsum, G rows.
__global__ __launch_bounds__(256) void k_ATG(const float* __restrict__ ctx,
                                             float* __restrict__ G) {
    const int b  = blockIdx.y;
    const int i0 = blockIdx.x << 5;
    const int t  = threadIdx.x;
    __shared__ float sm[LQ], sw[LQ];
    __shared__ float As[32][33];
    __shared__ float scs[32];
    for (int k = t; k < LQ; k += 256) {
        sm[k] = g_m [b * LQ + k];
        sw[k] = g_w2[b * LQ + k];
    }
    __syncthreads();

    const int ii = t >> 3;           // 0..31 (i within tile for read phase)
    const int jq = (t & 7) * 4;      // 0..28 (j within 32-chunk)
    float cs = 0.f;

    for (int jt = 0; jt < 32; jt++) {
        int j = jt * 32 + jq;
        float4 s = *(const float4*)(g_S + ((size_t)(b * LC + i0 + ii)) * LQ + j);
        float a0 = __expf(s.x - sm[j + 0]) * sw[j + 0];
        float a1 = __expf(s.y - sm[j + 1]) * sw[j + 1];
        float a2 = __expf(s.z - sm[j + 2]) * sw[j + 2];
        float a3 = __expf(s.w - sm[j + 3]) * sw[j + 3];
        cs += (a0 + a1) + (a2 + a3);
        As[ii][jq + 0] = rna_tf32(a0);
        As[ii][jq + 1] = rna_tf32(a1);
        As[ii][jq + 2] = rna_tf32(a2);
        As[ii][jq + 3] = rna_tf32(a3);
        __syncthreads();
        // transposed write: row = j, 32 i's contiguous
        int jj = t >> 3;             // j within chunk
        int iq = (t & 7) * 4;        // i within tile
        float4 v = make_float4(As[iq + 0][jj], As[iq + 1][jj],
                               As[iq + 2][jj], As[iq + 3][jj]);
        *(float4*)(g_At + ((size_t)(b * LQ + jt * 32 + jj)) * LC + i0 + iq) = v;
        __syncthreads();
    }
    // reduce cs over the 8 threads sharing ii (consecutive lanes)
    cs += __shfl_xor_sync(~0u, cs, 4);
    cs += __shfl_xor_sync(~0u, cs, 2);
    cs += __shfl_xor_sync(~0u, cs, 1);
    if ((t & 7) == 0) scs[ii] = cs;
    __syncthreads();
    // write G rows: 32 rows x 128 float4 (= 2*D_ floats)
    for (int idx = t; idx < 32 * 128; idx += 256) {
        int row = idx >> 7, c = idx & 127;
        float4 v = ((const float4*)(ctx + ((size_t)(b * LC + i0 + row)) * D_))[c];
        float s = scs[row];
        float4* g4 = (float4*)(G + ((size_t)(b * LC + i0 + row)) * 2 * D_);
        g4[c] = v;
        g4[128 + c] = make_float4(v.x * s, v.y * s, v.z * s, v.w * s);
    }
}

// ---------------- launch -----------------------------------------------------
extern "C" void kernel_launch(void* const* d_in, const int* in_sizes, int n_in,
                              void* d_out, int out_size) {
    const float *ctx = nullptr, *q = nullptr, *w = nullptr;
    for (int i = 0; i < n_in; i++) {
        if      (in_sizes[i] == B_ * LC * D_) ctx = (const float*)d_in[i];
        else if (in_sizes[i] == LQ * D_)      q   = (const float*)d_in[i];
        else if (in_sizes[i] == 3 * D_)       w   = (const float*)d_in[i];
    }
    float* G = (float*)d_out;                              // (B, LC, 2D)
    float* H = (float*)d_out + (size_t)B_ * LC * 2 * D_;   // (B, LQ, D)

    cudaFuncSetAttribute(k_mma<0>, cudaFuncAttributeMaxDynamicSharedMemorySize, GEMM_SMEM);
    cudaFuncSetAttribute(k_mma<1>, cudaFuncAttributeMaxDynamicSharedMemorySize, GEMM_SMEM);

    k_bias   <<<(B_ * LC + LQ + 7) / 8, 256>>>(ctx, q, w);
    k_prep   <<<dim3(D_ / 32, LC / 32, B_), dim3(32, 8)>>>(ctx);
    k_qm     <<<LQ, 128>>>(q, w);
    k_mma<0> <<<dim3(LQ / 128, LC / 256, B_), 256, GEMM_SMEM>>>(nullptr);
    k_stats1 <<<dim3(LQ / 128, B_, 4), dim3(128, 4)>>>();
    k_stats2 <<<B_ * LQ / 256, 256>>>();
    k_ATG    <<<dim3(LC / 32, B_), 256>>>(ctx, G);
    k_mma<1> <<<dim3(D_ / 128, LQ / 256, B_), 256, GEMM_SMEM>>>(H);
}

// round 8
// speedup vs baseline: 1.1610x; 1.0724x over previous
#include <cuda_runtime.h>
#include <math.h>
#include <stdint.h>

#define B_  16
#define LC  2048
#define LQ  1024
#define D_  512

// ---------------- scratch (device globals; cudaMalloc forbidden) ----------
__device__ float g_S  [(size_t)B_ * LC * LQ];  // 128 MiB: S[b,i,j]
__device__ float g_At [(size_t)B_ * LQ * LC];  // 128 MiB: A^T[b,j,i] (tf32-rounded)
__device__ float g_c32[(size_t)B_ * LC * D_];  // 64 MiB : rna(ctx) [b,i,d]
__device__ float g_cT [(size_t)B_ * D_ * LC];  // 64 MiB : rna(ctx)^T [b,d,i]
__device__ float g_qm [(size_t)LQ * D_];       // 2 MiB  : rna(q * wm) [j,k]
__device__ float g_cb [B_ * LC];               // context @ wc
__device__ float g_m  [B_ * LQ];               // softmax max over i per (b,j)
__device__ float g_w2 [B_ * LQ];               // qmask[j] / Z[b,j]
__device__ float g_qmask[LQ];
__device__ float g_mp [4][B_ * LQ];            // strip partial max
__device__ float g_zp [4][B_ * LQ];            // strip partial Z

// ---------------- helpers ---------------------------------------------------
__device__ __forceinline__ uint32_t smem_u32(const void* p) {
    uint32_t a;
    asm("{ .reg .u64 t; cvta.to.shared.u64 t, %1; cvt.u32.u64 %0, t; }" : "=r"(a) : "l"(p));
    return a;
}
__device__ __forceinline__ float rna_tf32(float x) {
    float y; asm("cvt.rna.tf32.f32 %0, %1;" : "=f"(y) : "f"(x)); return y;
}
#define CP16(sm, gp) \
    asm volatile("cp.async.cg.shared.global [%0], [%1], 16;" :: "r"(sm), "l"(gp))
#define CP_COMMIT() asm volatile("cp.async.commit_group;" ::: "memory")

#define LDSM4(r0, r1, r2, r3, addr) \
    asm volatile("ldmatrix.sync.aligned.m8n8.x4.shared.b16 {%0,%1,%2,%3}, [%4];" \
        : "=r"(r0), "=r"(r1), "=r"(r2), "=r"(r3) : "r"(addr))

#define MMA(c, a, b) \
    asm volatile("mma.sync.aligned.m16n8k8.row.col.f32.tf32.tf32.f32 " \
        "{%0,%1,%2,%3},{%4,%5,%6,%7},{%8,%9},{%0,%1,%2,%3};" \
        : "+f"((c)[0]), "+f"((c)[1]), "+f"((c)[2]), "+f"((c)[3]) \
        : "r"((a)[0]), "r"((a)[1]), "r"((a)[2]), "r"((a)[3]), \
          "r"((b)[0]), "r"((b)[1]))

// ---------------- kernel: cb = C@wc per row, qmask per query row ----------
__global__ void k_bias(const float* __restrict__ ctx,
                       const float* __restrict__ q,
                       const float* __restrict__ w) {
    int gwarp = (blockIdx.x * blockDim.x + threadIdx.x) >> 5;
    int lane  = threadIdx.x & 31;
    const int nrows = B_ * LC + LQ;
    if (gwarp >= nrows) return;
    if (gwarp < B_ * LC) {
        const float4* row = (const float4*)(ctx + (size_t)gwarp * D_);
        const float4* wc4 = (const float4*)w;
        float s = 0.f;
        #pragma unroll 4
        for (int k = lane; k < D_ / 4; k += 32) {
            float4 a = row[k], b = wc4[k];
            s += a.x * b.x + a.y * b.y + a.z * b.z + a.w * b.w;
        }
        #pragma unroll
        for (int o = 16; o; o >>= 1) s += __shfl_xor_sync(~0u, s, o);
        if (!lane) g_cb[gwarp] = s;
    } else {
        int j = gwarp - B_ * LC;
        const float4* row = (const float4*)(q + (size_t)j * D_);
        float s = 0.f;
        #pragma unroll 4
        for (int k = lane; k < D_ / 4; k += 32) {
            float4 a = row[k];
            s += a.x + a.y + a.z + a.w;
        }
        #pragma unroll
        for (int o = 16; o; o >>= 1) s += __shfl_xor_sync(~0u, s, o);
        if (!lane) g_qmask[j] = (s != 0.0f) ? 1.0f : 0.0f;
    }
}

// ---------------- kernel: round ctx -> c32 [i][d], transpose -> cT [d][i] ---
__global__ void k_prep(const float* __restrict__ ctx) {
    __shared__ float t[32][33];
    int b = blockIdx.z, i0 = blockIdx.y << 5, d0 = blockIdx.x << 5;
    int tx = threadIdx.x, ty = threadIdx.y;
    #pragma unroll
    for (int q = 0; q < 4; q++) {
        int r = ty + q * 8;
        float v = rna_tf32(ctx[((size_t)b * LC + i0 + r) * D_ + d0 + tx]);
        g_c32[((size_t)b * LC + i0 + r) * D_ + d0 + tx] = v;
        t[r][tx] = v;
    }
    __syncthreads();
    #pragma unroll
    for (int q = 0; q < 4; q++) {
        int r = ty + q * 8;
        g_cT[((size_t)b * D_ + d0 + r) * LC + i0 + tx] = t[tx][r];
    }
}

// ---------------- kernel: qm[j,k] = rna(q[j,k] * wm[k]) --------------------
__global__ void k_qm(const float* __restrict__ q, const float* __restrict__ w) {
    int j = blockIdx.x, t = threadIdx.x;
    const float4* q4 = (const float4*)(q + (size_t)j * D_);
    const float4* w4 = (const float4*)(w + 2 * D_);
    float4 a = q4[t], b = w4[t];
    float4 o = { rna_tf32(a.x * b.x), rna_tf32(a.y * b.y),
                 rna_tf32(a.z * b.z), rna_tf32(a.w * b.w) };
    ((float4*)(g_qm + (size_t)j * D_))[t] = o;
}

// ---------------- unified K-major tf32 GEMM --------------------------------
// Block 128(m) x 128(n), 128 threads, 4 warps of 64x64, BK=32, 3-stage
// cp.async, 2 CTAs/SM so bubbles of one CTA hide under the other's MMAs.
// MODE 0: m=i (128 of LC), n=j, K=D_  : S = c32 · qm^T + cb
// MODE 1: m=j (128 of LQ), n=d, K=LC : H = At · cT^T
#define ASZ (128 * 36)            // A floats per stage
#define BSZ (128 * 36)            // B floats per stage
#define STG (ASZ + BSZ)           // 9216 floats = 36864 B
#define GEMM_SMEM (3 * STG * 4)   // 110592 B

template<int MODE>
__global__ __launch_bounds__(128, 2) void k_mma(float* __restrict__ gOut) {
    constexpr int KTOT = MODE ? LC : D_;
    constexpr int NKC  = KTOT / 32;

    extern __shared__ float sh[];
    const int tid = threadIdx.x;
    const int b   = blockIdx.z;
    const int x0  = blockIdx.x * 128;   // n origin
    const int y0  = blockIdx.y * 128;   // m origin

    const float* Abase = MODE ? g_At + ((size_t)b * LQ + y0) * LC
                              : g_c32 + ((size_t)b * LC + y0) * D_;
    const float* Bbase = MODE ? g_cT + ((size_t)b * D_ + x0) * LC
                              : g_qm + (size_t)x0 * D_;

    auto load = [&](int c, int st) {
        float* dA = sh + st * STG;
        float* dB = dA + ASZ;
        const int k0 = c * 32;
        #pragma unroll
        for (int p = 0; p < 8; p++) {               // A: 128 rows x 8 segs
            int idx = tid + p * 128;
            int row = idx >> 3, seg = idx & 7;
            CP16(smem_u32(dA + row * 36 + seg * 4),
                 Abase + (size_t)row * KTOT + k0 + seg * 4);
        }
        #pragma unroll
        for (int p = 0; p < 8; p++) {               // B: 128 rows x 8 segs
            int idx = tid + p * 128;
            int row = idx >> 3, seg = idx & 7;
            CP16(smem_u32(dB + row * 36 + seg * 4),
                 Bbase + (size_t)row * KTOT + k0 + seg * 4);
        }
    };

    const int lane  = tid & 31, wrp = tid >> 5;
    const int mbase = (wrp & 1) * 64;               // 2 warps along m
    const int nbase = (wrp >> 1) * 64;              // 2 warps along n
    const int lr    = lane >> 2, lk = lane & 3;

    // ldmatrix per-thread byte offsets (within a stage)
    // A matrices order: (r+0,kk),(r+8,kk),(r+0,kk+4),(r+8,kk+4)
    const uint32_t aoff = ((mbase + ((lane >> 3) & 1) * 8 + (lane & 7)) * 36
                           + ((lane >> 4) & 1) * 4) * 4;
    // B matrices order: (n+0,kk),(n+0,kk+4),(n+8,kk),(n+8,kk+4)
    const uint32_t boff = ((nbase + ((lane >> 4) & 1) * 8 + (lane & 7)) * 36
                           + ((lane >> 3) & 1) * 4) * 4;

    float acc[4][8][4];
    #pragma unroll
    for (int mt = 0; mt < 4; mt++)
        #pragma unroll
        for (int nt = 0; nt < 8; nt++)
            #pragma unroll
            for (int e = 0; e < 4; e++) acc[mt][nt][e] = 0.f;

    auto compute = [&](int st) {
        const uint32_t aB = smem_u32(sh + st * STG) + aoff;
        const uint32_t bB = smem_u32(sh + st * STG + ASZ) + boff;
        #pragma unroll
        for (int kk = 0; kk < 32; kk += 8) {
            uint32_t af[4][4], bf[8][2];
            #pragma unroll
            for (int mt = 0; mt < 4; mt++)
                LDSM4(af[mt][0], af[mt][1], af[mt][2], af[mt][3],
                      aB + (mt * 16 * 36 + kk) * 4);
            #pragma unroll
            for (int p = 0; p < 4; p++)
                LDSM4(bf[2 * p][0], bf[2 * p][1], bf[2 * p + 1][0], bf[2 * p + 1][1],
                      bB + (p * 16 * 36 + kk) * 4);
            #pragma unroll
            for (int mt = 0; mt < 4; mt++)
                #pragma unroll
                for (int nt = 0; nt < 8; nt++)
                    MMA(acc[mt][nt], af[mt], bf[nt]);
        }
    };

    load(0, 0); CP_COMMIT();
    load(1, 1); CP_COMMIT();
    int st_c = 0, st_l = 2;                         // compute stage, load stage
    for (int c = 0; c < NKC; c++) {
        asm volatile("cp.async.wait_group 1;" ::: "memory");
        __syncthreads();                 // all warps finished stage st_l (c-1)
        if (c + 2 < NKC) load(c + 2, st_l);
        CP_COMMIT();
        compute(st_c);
        st_c = (st_c == 2) ? 0 : st_c + 1;
        st_l = (st_l == 2) ? 0 : st_l + 1;
    }

    // ---- epilogue
    if (MODE == 0) {
        #pragma unroll
        for (int mt = 0; mt < 4; mt++) {
            int i = y0 + mbase + mt * 16 + lr;
            float c0 = g_cb[b * LC + i];
            float c8 = g_cb[b * LC + i + 8];
            #pragma unroll
            for (int nt = 0; nt < 8; nt++) {
                int j = x0 + nbase + nt * 8 + 2 * lk;
                float2 v0 = make_float2(acc[mt][nt][0] + c0, acc[mt][nt][1] + c0);
                float2 v1 = make_float2(acc[mt][nt][2] + c8, acc[mt][nt][3] + c8);
                *(float2*)(g_S + ((size_t)(b * LC + i)) * LQ + j)     = v0;
                *(float2*)(g_S + ((size_t)(b * LC + i + 8)) * LQ + j) = v1;
            }
        }
    } else {
        #pragma unroll
        for (int mt = 0; mt < 4; mt++) {
            int j = y0 + mbase + mt * 16 + lr;
            #pragma unroll
            for (int nt = 0; nt < 8; nt++) {
                int d = x0 + nbase + nt * 8 + 2 * lk;
                float2 v0 = make_float2(acc[mt][nt][0], acc[mt][nt][1]);
                float2 v1 = make_float2(acc[mt][nt][2], acc[mt][nt][3]);
                *(float2*)(gOut + ((size_t)(b * LQ + j)) * D_ + d)     = v0;
                *(float2*)(gOut + ((size_t)(b * LQ + j + 8)) * D_ + d) = v1;
            }
        }
    }
}

// ---------------- kernel: strip-partial max + Z over i (phase 1) -----------
__global__ void k_stats1() {
    const int b  = blockIdx.y;
    const int j  = blockIdx.x * 128 + threadIdx.x;
    const int st = blockIdx.z;
    const int ty = threadIdx.y;
    const int ibeg = st * (LC / 4);
    const float* Sp = g_S + (size_t)b * LC * LQ + j;
    float m = -1e30f, Z = 0.f;
    for (int i = ibeg + ty; i < ibeg + LC / 4; i += 4) {
        float s = Sp[(size_t)i * LQ];
        if (s > m) { Z *= __expf(m - s); m = s; }
        Z += __expf(s - m);
    }
    __shared__ float smm[4][128], smz[4][128];
    smm[ty][threadIdx.x] = m;
    smz[ty][threadIdx.x] = Z;
    __syncthreads();
    if (ty == 0) {
        float mm = m;
        #pragma unroll
        for (int t = 1; t < 4; t++) mm = fmaxf(mm, smm[t][threadIdx.x]);
        float ZZ = 0.f;
        #pragma unroll
        for (int t = 0; t < 4; t++) ZZ += smz[t][threadIdx.x] * __expf(smm[t][threadIdx.x] - mm);
        g_mp[st][b * LQ + j] = mm;
        g_zp[st][b * LQ + j] = ZZ;
    }
}

// ---------------- kernel: combine strips (phase 2) --------------------------
__global__ void k_stats2() {
    int idx = blockIdx.x * blockDim.x + threadIdx.x;
    float m0 = g_mp[0][idx], m1 = g_mp[1][idx];
    float m2 = g_mp[2][idx], m3 = g_mp[3][idx];
    float M = fmaxf(fmaxf(m0, m1), fmaxf(m2, m3));
    float Z = g_zp[0][idx] * __expf(m0 - M) + g_zp[1][idx] * __expf(m1 - M)
            + g_zp[2][idx] * __expf(m2 - M) + g_zp[3][idx] * __expf(m3 - M);
    g_m [idx] = M;
    g_w2[idx] = g_qmask[idx & (LQ - 1)] / Z;
}

// ---------------- kernel: A^T tiles + colsum + G (fused) --------------------
__global__ __launch_bounds__(256) void k_ATG(const float* __restrict__ ctx,
                                             float* __restrict__ G) {
    const int b  = blockIdx.y;
    const int i0 = blockIdx.x << 5;
    const int t  = threadIdx.x;
    __shared__ float sm[LQ], sw[LQ];
    __shared__ float As[32][33];
    __shared__ float scs[32];
    for (int k = t; k < LQ; k += 256) {
        sm[k] = g_m [b * LQ + k];
        sw[k] = g_w2[b * LQ + k];
    }
    __syncthreads();

    const int ii = t >> 3;           // 0..31 (i within tile for read phase)
    const int jq = (t & 7) * 4;      // 0..28 (j within 32-chunk)
    float cs = 0.f;

    for (int jt = 0; jt < 32; jt++) {
        int j = jt * 32 + jq;
        float4 s = *(const float4*)(g_S + ((size_t)(b * LC + i0 + ii)) * LQ + j);
        float a0 = __expf(s.x - sm[j + 0]) * sw[j + 0];
        float a1 = __expf(s.y - sm[j + 1]) * sw[j + 1];
        float a2 = __expf(s.z - sm[j + 2]) * sw[j + 2];
        float a3 = __expf(s.w - sm[j + 3]) * sw[j + 3];
        cs += (a0 + a1) + (a2 + a3);
        As[ii][jq + 0] = rna_tf32(a0);
        As[ii][jq + 1] = rna_tf32(a1);
        As[ii][jq + 2] = rna_tf32(a2);
        As[ii][jq + 3] = rna_tf32(a3);
        __syncthreads();
        int jj = t >> 3;
        int iq = (t & 7) * 4;
        float4 v = make_float4(As[iq + 0][jj], As[iq + 1][jj],
                               As[iq + 2][jj], As[iq + 3][jj]);
        *(float4*)(g_At + ((size_t)(b * LQ + jt * 32 + jj)) * LC + i0 + iq) = v;
        __syncthreads();
    }
    cs += __shfl_xor_sync(~0u, cs, 4);
    cs += __shfl_xor_sync(~0u, cs, 2);
    cs += __shfl_xor_sync(~0u, cs, 1);
    if ((t & 7) == 0) scs[ii] = cs;
    __syncthreads();
    for (int idx = t; idx < 32 * 128; idx += 256) {
        int row = idx >> 7, c = idx & 127;
        float4 v = ((const float4*)(ctx + ((size_t)(b * LC + i0 + row)) * D_))[c];
        float s = scs[row];
        float4* g4 = (float4*)(G + ((size_t)(b * LC + i0 + row)) * 2 * D_);
        g4[c] = v;
        g4[128 + c] = make_float4(v.x * s, v.y * s, v.z * s, v.w * s);
    }
}

// ---------------- launch -----------------------------------------------------
extern "C" void kernel_launch(void* const* d_in, const int* in_sizes, int n_in,
                              void* d_out, int out_size) {
    const float *ctx = nullptr, *q = nullptr, *w = nullptr;
    for (int i = 0; i < n_in; i++) {
        if      (in_sizes[i] == B_ * LC * D_) ctx = (const float*)d_in[i];
        else if (in_sizes[i] == LQ * D_)      q   = (const float*)d_in[i];
        else if (in_sizes[i] == 3 * D_)       w   = (const float*)d_in[i];
    }
    float* G = (float*)d_out;                              // (B, LC, 2D)
    float* H = (float*)d_out + (size_t)B_ * LC * 2 * D_;   // (B, LQ, D)

    cudaFuncSetAttribute(k_mma<0>, cudaFuncAttributeMaxDynamicSharedMemorySize, GEMM_SMEM);
    cudaFuncSetAttribute(k_mma<1>, cudaFuncAttributeMaxDynamicSharedMemorySize, GEMM_SMEM);

    k_bias   <<<(B_ * LC + LQ + 7) / 8, 256>>>(ctx, q, w);
    k_prep   <<<dim3(D_ / 32, LC / 32, B_), dim3(32, 8)>>>(ctx);
    k_qm     <<<LQ, 128>>>(q, w);
    k_mma<0> <<<dim3(LQ / 128, LC / 128, B_), 128, GEMM_SMEM>>>(nullptr);
    k_stats1 <<<dim3(LQ / 128, B_, 4), dim3(128, 4)>>>();
    k_stats2 <<<B_ * LQ / 256, 256>>>();
    k_ATG    <<<dim3(LC / 32, B_), 256>>>(ctx, G);
    k_mma<1> <<<dim3(D_ / 128, LQ / 128, B_), 128, GEMM_SMEM>>>(H);
}

// round 9
// speedup vs baseline: 1.1863x; 1.0218x over previous
#include <cuda_runtime.h>
#include <math.h>
#include <stdint.h>

#define B_  16
#define LC  2048
#define LQ  1024
#define D_  512

// ---------------- scratch (device globals; cudaMalloc forbidden) ----------
__device__ float g_S  [(size_t)B_ * LC * LQ];  // 128 MiB: S[b,i,j]
__device__ float g_At [(size_t)B_ * LQ * LC];  // 128 MiB: A^T[b,j,i] (tf32-rounded)
__device__ float g_c32[(size_t)B_ * LC * D_];  // 64 MiB : rna(ctx) [b,i,d]
__device__ float g_cT [(size_t)B_ * D_ * LC];  // 64 MiB : rna(ctx)^T [b,d,i]
__device__ float g_qm [(size_t)LQ * D_];       // 2 MiB  : rna(q * wm) [j,k]
__device__ float g_cb [B_ * LC];               // context @ wc
__device__ float g_m  [B_ * LQ];               // softmax max over i per (b,j)
__device__ float g_w2 [B_ * LQ];               // qmask[j] / Z[b,j]
__device__ float g_qmask[LQ];
__device__ float g_mp [16][B_ * LQ];           // per-128-i-strip partial max
__device__ float g_zp [16][B_ * LQ];           // per-128-i-strip partial Z

// ---------------- helpers ---------------------------------------------------
__device__ __forceinline__ uint32_t smem_u32(const void* p) {
    uint32_t a;
    asm("{ .reg .u64 t; cvta.to.shared.u64 t, %1; cvt.u32.u64 %0, t; }" : "=r"(a) : "l"(p));
    return a;
}
__device__ __forceinline__ float rna_tf32(float x) {
    float y; asm("cvt.rna.tf32.f32 %0, %1;" : "=f"(y) : "f"(x)); return y;
}
#define CP16(sm, gp) \
    asm volatile("cp.async.cg.shared.global [%0], [%1], 16;" :: "r"(sm), "l"(gp))
#define CP_COMMIT() asm volatile("cp.async.commit_group;" ::: "memory")

#define LDSM4(r0, r1, r2, r3, addr) \
    asm volatile("ldmatrix.sync.aligned.m8n8.x4.shared.b16 {%0,%1,%2,%3}, [%4];" \
        : "=r"(r0), "=r"(r1), "=r"(r2), "=r"(r3) : "r"(addr))

#define MMA(c, a, b) \
    asm volatile("mma.sync.aligned.m16n8k8.row.col.f32.tf32.tf32.f32 " \
        "{%0,%1,%2,%3},{%4,%5,%6,%7},{%8,%9},{%0,%1,%2,%3};" \
        : "+f"((c)[0]), "+f"((c)[1]), "+f"((c)[2]), "+f"((c)[3]) \
        : "r"((a)[0]), "r"((a)[1]), "r"((a)[2]), "r"((a)[3]), \
          "r"((b)[0]), "r"((b)[1]))

// ---------------- kernel: cb = C@wc per row, qmask per query row ----------
__global__ void k_bias(const float* __restrict__ ctx,
                       const float* __restrict__ q,
                       const float* __restrict__ w) {
    int gwarp = (blockIdx.x * blockDim.x + threadIdx.x) >> 5;
    int lane  = threadIdx.x & 31;
    const int nrows = B_ * LC + LQ;
    if (gwarp >= nrows) return;
    if (gwarp < B_ * LC) {
        const float4* row = (const float4*)(ctx + (size_t)gwarp * D_);
        const float4* wc4 = (const float4*)w;
        float s = 0.f;
        #pragma unroll 4
        for (int k = lane; k < D_ / 4; k += 32) {
            float4 a = row[k], b = wc4[k];
            s += a.x * b.x + a.y * b.y + a.z * b.z + a.w * b.w;
        }
        #pragma unroll
        for (int o = 16; o; o >>= 1) s += __shfl_xor_sync(~0u, s, o);
        if (!lane) g_cb[gwarp] = s;
    } else {
        int j = gwarp - B_ * LC;
        const float4* row = (const float4*)(q + (size_t)j * D_);
        float s = 0.f;
        #pragma unroll 4
        for (int k = lane; k < D_ / 4; k += 32) {
            float4 a = row[k];
            s += a.x + a.y + a.z + a.w;
        }
        #pragma unroll
        for (int o = 16; o; o >>= 1) s += __shfl_xor_sync(~0u, s, o);
        if (!lane) g_qmask[j] = (s != 0.0f) ? 1.0f : 0.0f;
    }
}

// ---------------- kernel: round ctx -> c32 [i][d], transpose -> cT [d][i] ---
__global__ void k_prep(const float* __restrict__ ctx) {
    __shared__ float t[32][33];
    int b = blockIdx.z, i0 = blockIdx.y << 5, d0 = blockIdx.x << 5;
    int tx = threadIdx.x, ty = threadIdx.y;
    #pragma unroll
    for (int q = 0; q < 4; q++) {
        int r = ty + q * 8;
        float v = rna_tf32(ctx[((size_t)b * LC + i0 + r) * D_ + d0 + tx]);
        g_c32[((size_t)b * LC + i0 + r) * D_ + d0 + tx] = v;
        t[r][tx] = v;
    }
    __syncthreads();
    #pragma unroll
    for (int q = 0; q < 4; q++) {
        int r = ty + q * 8;
        g_cT[((size_t)b * D_ + d0 + r) * LC + i0 + tx] = t[tx][r];
    }
}

// ---------------- kernel: qm[j,k] = rna(q[j,k] * wm[k]) --------------------
__global__ void k_qm(const float* __restrict__ q, const float* __restrict__ w) {
    int j = blockIdx.x, t = threadIdx.x;
    const float4* q4 = (const float4*)(q + (size_t)j * D_);
    const float4* w4 = (const float4*)(w + 2 * D_);
    float4 a = q4[t], b = w4[t];
    float4 o = { rna_tf32(a.x * b.x), rna_tf32(a.y * b.y),
                 rna_tf32(a.z * b.z), rna_tf32(a.w * b.w) };
    ((float4*)(g_qm + (size_t)j * D_))[t] = o;
}

// ---------------- unified K-major tf32 GEMM --------------------------------
// Block 128(m) x 128(n), 128 threads, 4 warps of 64x64, BK=32, 3-stage
// cp.async, 2 CTAs/SM.  MODE 0 epilogue also emits per-strip softmax
// partials (max/Z over the tile's 128 i's) -> g_mp/g_zp[blockIdx.y].
// MODE 0: m=i (128 of LC), n=j, K=D_  : S = c32 · qm^T + cb
// MODE 1: m=j (128 of LQ), n=d, K=LC : H = At · cT^T
#define ASZ (128 * 36)            // A floats per stage
#define BSZ (128 * 36)            // B floats per stage
#define STG (ASZ + BSZ)           // 9216 floats = 36864 B
#define GEMM_SMEM (3 * STG * 4)   // 110592 B

template<int MODE>
__global__ __launch_bounds__(128, 2) void k_mma(float* __restrict__ gOut) {
    constexpr int KTOT = MODE ? LC : D_;
    constexpr int NKC  = KTOT / 32;

    extern __shared__ float sh[];
    const int tid = threadIdx.x;
    const int b   = blockIdx.z;
    const int x0  = blockIdx.x * 128;   // n origin
    const int y0  = blockIdx.y * 128;   // m origin

    const float* Abase = MODE ? g_At + ((size_t)b * LQ + y0) * LC
                              : g_c32 + ((size_t)b * LC + y0) * D_;
    const float* Bbase = MODE ? g_cT + ((size_t)b * D_ + x0) * LC
                              : g_qm + (size_t)x0 * D_;

    auto load = [&](int c, int st) {
        float* dA = sh + st * STG;
        float* dB = dA + ASZ;
        const int k0 = c * 32;
        #pragma unroll
        for (int p = 0; p < 8; p++) {               // A: 128 rows x 8 segs
            int idx = tid + p * 128;
            int row = idx >> 3, seg = idx & 7;
            CP16(smem_u32(dA + row * 36 + seg * 4),
                 Abase + (size_t)row * KTOT + k0 + seg * 4);
        }
        #pragma unroll
        for (int p = 0; p < 8; p++) {               // B: 128 rows x 8 segs
            int idx = tid + p * 128;
            int row = idx >> 3, seg = idx & 7;
            CP16(smem_u32(dB + row * 36 + seg * 4),
                 Bbase + (size_t)row * KTOT + k0 + seg * 4);
        }
    };

    const int lane  = tid & 31, wrp = tid >> 5;
    const int mbase = (wrp & 1) * 64;               // 2 warps along m
    const int nbase = (wrp >> 1) * 64;              // 2 warps along n
    const int lr    = lane >> 2, lk = lane & 3;

    const uint32_t aoff = ((mbase + ((lane >> 3) & 1) * 8 + (lane & 7)) * 36
                           + ((lane >> 4) & 1) * 4) * 4;
    const uint32_t boff = ((nbase + ((lane >> 4) & 1) * 8 + (lane & 7)) * 36
                           + ((lane >> 3) & 1) * 4) * 4;

    float acc[4][8][4];
    #pragma unroll
    for (int mt = 0; mt < 4; mt++)
        #pragma unroll
        for (int nt = 0; nt < 8; nt++)
            #pragma unroll
            for (int e = 0; e < 4; e++) acc[mt][nt][e] = 0.f;

    auto compute = [&](int st) {
        const uint32_t aB = smem_u32(sh + st * STG) + aoff;
        const uint32_t bB = smem_u32(sh + st * STG + ASZ) + boff;
        #pragma unroll
        for (int kk = 0; kk < 32; kk += 8) {
            uint32_t af[4][4], bf[8][2];
            #pragma unroll
            for (int mt = 0; mt < 4; mt++)
                LDSM4(af[mt][0], af[mt][1], af[mt][2], af[mt][3],
                      aB + (mt * 16 * 36 + kk) * 4);
            #pragma unroll
            for (int p = 0; p < 4; p++)
                LDSM4(bf[2 * p][0], bf[2 * p][1], bf[2 * p + 1][0], bf[2 * p + 1][1],
                      bB + (p * 16 * 36 + kk) * 4);
            #pragma unroll
            for (int mt = 0; mt < 4; mt++)
                #pragma unroll
                for (int nt = 0; nt < 8; nt++)
                    MMA(acc[mt][nt], af[mt], bf[nt]);
        }
    };

    load(0, 0); CP_COMMIT();
    load(1, 1); CP_COMMIT();
    int st_c = 0, st_l = 2;
    for (int c = 0; c < NKC; c++) {
        asm volatile("cp.async.wait_group 1;" ::: "memory");
        __syncthreads();
        if (c + 2 < NKC) load(c + 2, st_l);
        CP_COMMIT();
        compute(st_c);
        st_c = (st_c == 2) ? 0 : st_c + 1;
        st_l = (st_l == 2) ? 0 : st_l + 1;
    }

    // ---- epilogue
    if (MODE == 0) {
        // bias in-place + write S
        #pragma unroll
        for (int mt = 0; mt < 4; mt++) {
            int i = y0 + mbase + mt * 16 + lr;
            float c0 = g_cb[b * LC + i];
            float c8 = g_cb[b * LC + i + 8];
            #pragma unroll
            for (int nt = 0; nt < 8; nt++) {
                acc[mt][nt][0] += c0; acc[mt][nt][1] += c0;
                acc[mt][nt][2] += c8; acc[mt][nt][3] += c8;
                int j = x0 + nbase + nt * 8 + 2 * lk;
                *(float2*)(g_S + ((size_t)(b * LC + i)) * LQ + j) =
                    make_float2(acc[mt][nt][0], acc[mt][nt][1]);
                *(float2*)(g_S + ((size_t)(b * LC + i + 8)) * LQ + j) =
                    make_float2(acc[mt][nt][2], acc[mt][nt][3]);
            }
        }
        // per-thread stats over this thread's 8 i-values per column
        float pm[16], pz[16];
        #pragma unroll
        for (int nt = 0; nt < 8; nt++) {
            float m0 = -1e30f, m1 = -1e30f;
            #pragma unroll
            for (int mt = 0; mt < 4; mt++) {
                m0 = fmaxf(m0, fmaxf(acc[mt][nt][0], acc[mt][nt][2]));
                m1 = fmaxf(m1, fmaxf(acc[mt][nt][1], acc[mt][nt][3]));
            }
            float z0 = 0.f, z1 = 0.f;
            #pragma unroll
            for (int mt = 0; mt < 4; mt++) {
                z0 += __expf(acc[mt][nt][0] - m0) + __expf(acc[mt][nt][2] - m0);
                z1 += __expf(acc[mt][nt][1] - m1) + __expf(acc[mt][nt][3] - m1);
            }
            pm[2 * nt] = m0; pz[2 * nt] = z0;
            pm[2 * nt + 1] = m1; pz[2 * nt + 1] = z1;
        }
        // reduce across lr (lane bits 2..4)
        #pragma unroll
        for (int off = 4; off <= 16; off <<= 1) {
            #pragma unroll
            for (int c2 = 0; c2 < 16; c2++) {
                float mo = __shfl_xor_sync(~0u, pm[c2], off);
                float zo = __shfl_xor_sync(~0u, pz[c2], off);
                float mn = fmaxf(pm[c2], mo);
                pz[c2] = pz[c2] * __expf(pm[c2] - mn) + zo * __expf(mo - mn);
                pm[c2] = mn;
            }
        }
        // cross-m-warp combine in smem (stages no longer needed)
        float* red = sh;   // [2 mwarps][ m:128 | z:128 ]
        __syncthreads();
        if (lane < 4) {
            #pragma unroll
            for (int c2 = 0; c2 < 16; c2++) {
                int j = nbase + (c2 >> 1) * 8 + 2 * lane + (c2 & 1);
                red[(wrp & 1) * 256 + j]       = pm[c2];
                red[(wrp & 1) * 256 + 128 + j] = pz[c2];
            }
        }
        __syncthreads();
        if (tid < 128) {
            float ma = red[tid],      mb2 = red[256 + tid];
            float za = red[128 + tid], zb = red[384 + tid];
            float M = fmaxf(ma, mb2);
            float Z = za * __expf(ma - M) + zb * __expf(mb2 - M);
            g_mp[blockIdx.y][b * LQ + x0 + tid] = M;
            g_zp[blockIdx.y][b * LQ + x0 + tid] = Z;
        }
    } else {
        #pragma unroll
        for (int mt = 0; mt < 4; mt++) {
            int j = y0 + mbase + mt * 16 + lr;
            #pragma unroll
            for (int nt = 0; nt < 8; nt++) {
                int d = x0 + nbase + nt * 8 + 2 * lk;
                float2 v0 = make_float2(acc[mt][nt][0], acc[mt][nt][1]);
                float2 v1 = make_float2(acc[mt][nt][2], acc[mt][nt][3]);
                *(float2*)(gOut + ((size_t)(b * LQ + j)) * D_ + d)     = v0;
                *(float2*)(gOut + ((size_t)(b * LQ + j + 8)) * D_ + d) = v1;
            }
        }
    }
}

// ---------------- kernel: combine 16 strips ---------------------------------
__global__ void k_stats2() {
    int idx = blockIdx.x * blockDim.x + threadIdx.x;   // b*LQ + j
    float M = g_mp[0][idx];
    #pragma unroll
    for (int s = 1; s < 16; s++) M = fmaxf(M, g_mp[s][idx]);
    float Z = 0.f;
    #pragma unroll
    for (int s = 0; s < 16; s++) Z += g_zp[s][idx] * __expf(g_mp[s][idx] - M);
    g_m [idx] = M;
    g_w2[idx] = g_qmask[idx & (LQ - 1)] / Z;
}

// ---------------- kernel: A^T tiles + colsum + G (fused) --------------------
__global__ __launch_bounds__(256) void k_ATG(const float* __restrict__ ctx,
                                             float* __restrict__ G) {
    const int b  = blockIdx.y;
    const int i0 = blockIdx.x << 5;
    const int t  = threadIdx.x;
    __shared__ float sm[LQ], sw[LQ];
    __shared__ float As[32][33];
    __shared__ float scs[32];
    for (int k = t; k < LQ; k += 256) {
        sm[k] = g_m [b * LQ + k];
        sw[k] = g_w2[b * LQ + k];
    }
    __syncthreads();

    const int ii = t >> 3;
    const int jq = (t & 7) * 4;
    float cs = 0.f;

    for (int jt = 0; jt < 32; jt++) {
        int j = jt * 32 + jq;
        float4 s = *(const float4*)(g_S + ((size_t)(b * LC + i0 + ii)) * LQ + j);
        float a0 = __expf(s.x - sm[j + 0]) * sw[j + 0];
        float a1 = __expf(s.y - sm[j + 1]) * sw[j + 1];
        float a2 = __expf(s.z - sm[j + 2]) * sw[j + 2];
        float a3 = __expf(s.w - sm[j + 3]) * sw[j + 3];
        cs += (a0 + a1) + (a2 + a3);
        As[ii][jq + 0] = rna_tf32(a0);
        As[ii][jq + 1] = rna_tf32(a1);
        As[ii][jq + 2] = rna_tf32(a2);
        As[ii][jq + 3] = rna_tf32(a3);
        __syncthreads();
        int jj = t >> 3;
        int iq = (t & 7) * 4;
        float4 v = make_float4(As[iq + 0][jj], As[iq + 1][jj],
                               As[iq + 2][jj], As[iq + 3][jj]);
        *(float4*)(g_At + ((size_t)(b * LQ + jt * 32 + jj)) * LC + i0 + iq) = v;
        __syncthreads();
    }
    cs += __shfl_xor_sync(~0u, cs, 4);
    cs += __shfl_xor_sync(~0u, cs, 2);
    cs += __shfl_xor_sync(~0u, cs, 1);
    if ((t & 7) == 0) scs[ii] = cs;
    __syncthreads();
    for (int idx = t; idx < 32 * 128; idx += 256) {
        int row = idx >> 7, c = idx & 127;
        float4 v = ((const float4*)(ctx + ((size_t)(b * LC + i0 + row)) * D_))[c];
        float s = scs[row];
        float4* g4 = (float4*)(G + ((size_t)(b * LC + i0 + row)) * 2 * D_);
        g4[c] = v;
        g4[128 + c] = make_float4(v.x * s, v.y * s, v.z * s, v.w * s);
    }
}

// ---------------- launch -----------------------------------------------------
extern "C" void kernel_launch(void* const* d_in, const int* in_sizes, int n_in,
                              void* d_out, int out_size) {
    const float *ctx = nullptr, *q = nullptr, *w = nullptr;
    for (int i = 0; i < n_in; i++) {
        if      (in_sizes[i] == B_ * LC * D_) ctx = (const float*)d_in[i];
        else if (in_sizes[i] == LQ * D_)      q   = (const float*)d_in[i];
        else if (in_sizes[i] == 3 * D_)       w   = (const float*)d_in[i];
    }
    float* G = (float*)d_out;                              // (B, LC, 2D)
    float* H = (float*)d_out + (size_t)B_ * LC * 2 * D_;   // (B, LQ, D)

    cudaFuncSetAttribute(k_mma<0>, cudaFuncAttributeMaxDynamicSharedMemorySize, GEMM_SMEM);
    cudaFuncSetAttribute(k_mma<1>, cudaFuncAttributeMaxDynamicSharedMemorySize, GEMM_SMEM);

    k_bias   <<<(B_ * LC + LQ + 7) / 8, 256>>>(ctx, q, w);
    k_prep   <<<dim3(D_ / 32, LC / 32, B_), dim3(32, 8)>>>(ctx);
    k_qm     <<<LQ, 128>>>(q, w);
    k_mma<0> <<<dim3(LQ / 128, LC / 128, B_), 128, GEMM_SMEM>>>(nullptr);
    k_stats2 <<<B_ * LQ / 256, 256>>>();
    k_ATG    <<<dim3(LC / 32, B_), 256>>>(ctx, G);
    k_mma<1> <<<dim3(D_ / 128, LQ / 128, B_), 128, GEMM_SMEM>>>(H);
}